// round 1
// baseline (speedup 1.0000x reference)
#include <cuda_runtime.h>
#include <math.h>

#define Bn 8
#define C1 256
#define CH 128
#define C2 256
#define Hh 80
#define Ww 80
#define HW 6400
#define NT 9
#define KT 1152   /* CH * NT */
#define OC 27     /* 3 * NT offset-conv output channels */

// -------- scratch (device globals; no allocation allowed) --------
__device__ float g_y1[Bn*CH*HW];      // post cv1+bn1+silu
__device__ float g_off[Bn*18*HW];     // raw offsets (dy,dx per tap)
__device__ float g_mask[Bn*NT*HW];    // sigmoid(mask)
__device__ float g_z[Bn*CH*HW];       // post dcn+bn2+silu
__device__ float g_w1T[C1*CH];        // cv1_w transposed [c][o]
__device__ float g_offT[KT*OC];       // off_w transposed [k][o], k=c*9+n
__device__ float g_dcnT[KT*CH];       // dcn_w transposed [k][o]
__device__ float g_w2T[CH*C2];        // cv2_w transposed [c][o]
__device__ float g_s1[CH], g_t1[CH], g_s2[CH], g_t2[CH], g_s3[C2], g_t3[C2];

__device__ __forceinline__ float silu_f(float v) {
    return v / (1.f + __expf(-v));
}

// -------- prep: BN folding + weight transposes --------
__global__ void prep_kernel(const float* __restrict__ cv1w,
                            const float* __restrict__ bn1g, const float* __restrict__ bn1b,
                            const float* __restrict__ bn1m, const float* __restrict__ bn1v,
                            const float* __restrict__ offw, const float* __restrict__ dcnw,
                            const float* __restrict__ bn2g, const float* __restrict__ bn2b,
                            const float* __restrict__ bn2m, const float* __restrict__ bn2v,
                            const float* __restrict__ cv2w,
                            const float* __restrict__ bn3g, const float* __restrict__ bn3b,
                            const float* __restrict__ bn3m, const float* __restrict__ bn3v) {
    int idx0 = blockIdx.x * blockDim.x + threadIdx.x;
    int stride = gridDim.x * blockDim.x;
    for (int i = idx0; i < C1*CH; i += stride) { int c=i/CH, o=i%CH; g_w1T[i] = cv1w[o*C1+c]; }
    for (int i = idx0; i < KT*OC; i += stride) { int k=i/OC, o=i%OC; g_offT[i] = offw[o*KT+k]; }
    for (int i = idx0; i < KT*CH; i += stride) { int k=i/CH, o=i%CH; g_dcnT[i] = dcnw[o*KT+k]; }
    for (int i = idx0; i < CH*C2; i += stride) { int c=i/C2, o=i%C2; g_w2T[i] = cv2w[o*CH+c]; }
    for (int i = idx0; i < CH; i += stride) {
        float s = bn1g[i] * rsqrtf(bn1v[i] + 1e-5f);
        g_s1[i] = s; g_t1[i] = bn1b[i] - bn1m[i]*s;
        float s2 = bn2g[i] * rsqrtf(bn2v[i] + 1e-5f);
        g_s2[i] = s2; g_t2[i] = bn2b[i] - bn2m[i]*s2;
    }
    for (int i = idx0; i < C2; i += stride) {
        float s = bn3g[i] * rsqrtf(bn3v[i] + 1e-5f);
        g_s3[i] = s; g_t3[i] = bn3b[i] - bn3m[i]*s;
    }
}

// -------- k1: cv1 (1x1) + bn1 + silu.  GEMM 128o x 64px tile, K=256 --------
__global__ __launch_bounds__(256) void k1_cv1(const float* __restrict__ x) {
    __shared__ float ws[32][128];
    __shared__ float xs[32][64];
    int tid = threadIdx.x;
    int b = blockIdx.y;
    int p0 = blockIdx.x * 64;
    int o0 = (tid >> 4) * 8;
    int px0 = (tid & 15) * 4;
    float acc[8][4] = {};
    const float* xb = x + (size_t)b * C1 * HW + p0;
    for (int kc = 0; kc < C1; kc += 32) {
        for (int i = tid; i < 32*128; i += 256)
            ws[i>>7][i&127] = g_w1T[(kc + (i>>7))*CH + (i&127)];
        for (int i = tid; i < 32*64; i += 256)
            xs[i>>6][i&63] = xb[(kc + (i>>6))*HW + (i&63)];
        __syncthreads();
        #pragma unroll
        for (int kk = 0; kk < 32; kk++) {
            float4 a0 = *(const float4*)&ws[kk][o0];
            float4 a1 = *(const float4*)&ws[kk][o0+4];
            float4 bv = *(const float4*)&xs[kk][px0];
            float av[8] = {a0.x,a0.y,a0.z,a0.w,a1.x,a1.y,a1.z,a1.w};
            float bb[4] = {bv.x,bv.y,bv.z,bv.w};
            #pragma unroll
            for (int i = 0; i < 8; i++)
                #pragma unroll
                for (int j = 0; j < 4; j++) acc[i][j] += av[i]*bb[j];
        }
        __syncthreads();
    }
    #pragma unroll
    for (int i = 0; i < 8; i++) {
        int o = o0 + i;
        float s = g_s1[o], t = g_t1[o];
        float v0 = silu_f(acc[i][0]*s + t);
        float v1 = silu_f(acc[i][1]*s + t);
        float v2 = silu_f(acc[i][2]*s + t);
        float v3 = silu_f(acc[i][3]*s + t);
        *(float4*)(g_y1 + ((size_t)b*CH + o)*HW + p0 + px0) = make_float4(v0,v1,v2,v3);
    }
}

// -------- k2: offset conv 3x3 (27 out ch), on-the-fly im2col GEMM --------
__global__ __launch_bounds__(256) void k2_offconv(const float* __restrict__ offb) {
    __shared__ float ws[36][32];
    __shared__ float bs[36][64];
    int tid = threadIdx.x;
    int b = blockIdx.y;
    int p0 = blockIdx.x * 64;
    int o0 = (tid >> 6) * 8;     // 4 groups of 8 (o 24..31 padded/unused)
    int pxid = tid & 63;
    float acc[8] = {};
    const float* y1b = g_y1 + (size_t)b * CH * HW;
    for (int k0 = 0; k0 < KT; k0 += 36) {
        int c0 = k0 / 9;
        for (int i = tid; i < 36*64; i += 256) {
            int kk = i >> 6, pp = i & 63;
            int c = c0 + kk/9, n = kk - (kk/9)*9;
            int p = p0 + pp, h = p/80, w = p - h*80;
            int yy = h + n/3 - 1, xx = w + n%3 - 1;
            bs[kk][pp] = (yy >= 0 && yy < Hh && xx >= 0 && xx < Ww)
                         ? y1b[c*HW + yy*Ww + xx] : 0.f;
        }
        for (int i = tid; i < 36*32; i += 256) {
            int kk = i >> 5, o = i & 31;
            ws[kk][o] = (o < OC) ? g_offT[(k0+kk)*OC + o] : 0.f;
        }
        __syncthreads();
        #pragma unroll
        for (int kk = 0; kk < 36; kk++) {
            float bv = bs[kk][pxid];
            float4 a0 = *(const float4*)&ws[kk][o0];
            float4 a1 = *(const float4*)&ws[kk][o0+4];
            acc[0] += a0.x*bv; acc[1] += a0.y*bv; acc[2] += a0.z*bv; acc[3] += a0.w*bv;
            acc[4] += a1.x*bv; acc[5] += a1.y*bv; acc[6] += a1.z*bv; acc[7] += a1.w*bv;
        }
        __syncthreads();
    }
    int p = p0 + pxid;
    #pragma unroll
    for (int i = 0; i < 8; i++) {
        int o = o0 + i;
        if (o < OC) {
            float v = acc[i] + offb[o];
            if (o < 18) g_off[((size_t)b*18 + o)*HW + p] = v;
            else        g_mask[((size_t)b*NT + (o-18))*HW + p] = 1.f/(1.f + __expf(-v));
        }
    }
}

// -------- k3: DCNv2 + bn2 + silu.  Bilinear table + GEMM M=128, K=1152 --------
__global__ __launch_bounds__(256) void k3_dcn(const float* __restrict__ dcnb) {
    __shared__ float ws[36][128];
    __shared__ float bs[36][64];
    __shared__ int   ti[NT][64][4];
    __shared__ float tw[NT][64][4];
    int tid = threadIdx.x;
    int b = blockIdx.y;
    int p0 = blockIdx.x * 64;
    int o0 = (tid >> 4) * 8;
    int px0 = (tid & 15) * 4;

    // build bilinear sampling table (per tap, per pixel): 4 indices + 4 weights
    for (int e = tid; e < NT*64; e += 256) {
        int n = e >> 6, pp = e & 63;
        int p = p0 + pp, h = p/80, w = p - h*80;
        float m  = g_mask[((size_t)b*NT + n)*HW + p];
        float dy = g_off[((size_t)b*18 + 2*n    )*HW + p];
        float dx = g_off[((size_t)b*18 + 2*n + 1)*HW + p];
        float py = (float)(h - 1 + n/3) + dy;
        float px = (float)(w - 1 + n%3) + dx;
        float y0f = floorf(py), x0f = floorf(px);
        float fy = py - y0f, fx = px - x0f;
        int y0 = (int)y0f, x0 = (int)x0f;
        int y1i = y0 + 1, x1i = x0 + 1;
        float vy0 = (y0  >= 0 && y0  < Hh) ? 1.f : 0.f;
        float vy1 = (y1i >= 0 && y1i < Hh) ? 1.f : 0.f;
        float vx0 = (x0  >= 0 && x0  < Ww) ? 1.f : 0.f;
        float vx1 = (x1i >= 0 && x1i < Ww) ? 1.f : 0.f;
        int cy0 = min(max(y0, 0), Hh-1) * Ww;
        int cy1 = min(max(y1i,0), Hh-1) * Ww;
        int cx0 = min(max(x0, 0), Ww-1);
        int cx1 = min(max(x1i,0), Ww-1);
        ti[n][pp][0] = cy0 + cx0;  ti[n][pp][1] = cy0 + cx1;
        ti[n][pp][2] = cy1 + cx0;  ti[n][pp][3] = cy1 + cx1;
        tw[n][pp][0] = m * (1.f-fy)*(1.f-fx) * vy0*vx0;
        tw[n][pp][1] = m * (1.f-fy)*fx       * vy0*vx1;
        tw[n][pp][2] = m * fy*(1.f-fx)       * vy1*vx0;
        tw[n][pp][3] = m * fy*fx             * vy1*vx1;
    }
    __syncthreads();

    float acc[8][4] = {};
    const float* y1b = g_y1 + (size_t)b * CH * HW;
    for (int k0 = 0; k0 < KT; k0 += 36) {
        int c0 = k0 / 9;
        for (int i = tid; i < 36*64; i += 256) {
            int kk = i >> 6, pp = i & 63;
            int c = c0 + kk/9, n = kk - (kk/9)*9;
            const float* src = y1b + c*HW;
            float4 wv = *(const float4*)&tw[n][pp][0];
            int4   iv = *(const int4*)&ti[n][pp][0];
            bs[kk][pp] = wv.x*src[iv.x] + wv.y*src[iv.y]
                       + wv.z*src[iv.z] + wv.w*src[iv.w];
        }
        for (int i = tid; i < 36*128; i += 256)
            ws[i>>7][i&127] = g_dcnT[(k0 + (i>>7))*CH + (i&127)];
        __syncthreads();
        #pragma unroll
        for (int kk = 0; kk < 36; kk++) {
            float4 a0 = *(const float4*)&ws[kk][o0];
            float4 a1 = *(const float4*)&ws[kk][o0+4];
            float4 bv = *(const float4*)&bs[kk][px0];
            float av[8] = {a0.x,a0.y,a0.z,a0.w,a1.x,a1.y,a1.z,a1.w};
            float bb[4] = {bv.x,bv.y,bv.z,bv.w};
            #pragma unroll
            for (int i = 0; i < 8; i++)
                #pragma unroll
                for (int j = 0; j < 4; j++) acc[i][j] += av[i]*bb[j];
        }
        __syncthreads();
    }
    #pragma unroll
    for (int i = 0; i < 8; i++) {
        int o = o0 + i;
        float s = g_s2[o], t = g_t2[o], bias = dcnb[o];
        float v0 = silu_f((acc[i][0]+bias)*s + t);
        float v1 = silu_f((acc[i][1]+bias)*s + t);
        float v2 = silu_f((acc[i][2]+bias)*s + t);
        float v3 = silu_f((acc[i][3]+bias)*s + t);
        *(float4*)(g_z + ((size_t)b*CH + o)*HW + p0 + px0) = make_float4(v0,v1,v2,v3);
    }
}

// -------- k4: cv2 (1x1) + bn3 + silu + residual --------
__global__ __launch_bounds__(256) void k4_cv2(const float* __restrict__ x,
                                              float* __restrict__ out) {
    __shared__ float ws[32][128];
    __shared__ float zs[32][64];
    int tid = threadIdx.x;
    int b = blockIdx.y;
    int p0 = blockIdx.x * 64;
    int ob = blockIdx.z * 128;
    int o0 = (tid >> 4) * 8;
    int px0 = (tid & 15) * 4;
    float acc[8][4] = {};
    const float* zb = g_z + (size_t)b * CH * HW + p0;
    for (int kc = 0; kc < CH; kc += 32) {
        for (int i = tid; i < 32*128; i += 256)
            ws[i>>7][i&127] = g_w2T[(kc + (i>>7))*C2 + ob + (i&127)];
        for (int i = tid; i < 32*64; i += 256)
            zs[i>>6][i&63] = zb[(kc + (i>>6))*HW + (i&63)];
        __syncthreads();
        #pragma unroll
        for (int kk = 0; kk < 32; kk++) {
            float4 a0 = *(const float4*)&ws[kk][o0];
            float4 a1 = *(const float4*)&ws[kk][o0+4];
            float4 bv = *(const float4*)&zs[kk][px0];
            float av[8] = {a0.x,a0.y,a0.z,a0.w,a1.x,a1.y,a1.z,a1.w};
            float bb[4] = {bv.x,bv.y,bv.z,bv.w};
            #pragma unroll
            for (int i = 0; i < 8; i++)
                #pragma unroll
                for (int j = 0; j < 4; j++) acc[i][j] += av[i]*bb[j];
        }
        __syncthreads();
    }
    #pragma unroll
    for (int i = 0; i < 8; i++) {
        int o = ob + o0 + i;
        float s = g_s3[o], t = g_t3[o];
        size_t base = ((size_t)b*C2 + o)*HW + p0 + px0;
        float4 xr = *(const float4*)(x + base);
        float v0 = silu_f(acc[i][0]*s + t) + xr.x;
        float v1 = silu_f(acc[i][1]*s + t) + xr.y;
        float v2 = silu_f(acc[i][2]*s + t) + xr.z;
        float v3 = silu_f(acc[i][3]*s + t) + xr.w;
        *(float4*)(out + base) = make_float4(v0,v1,v2,v3);
    }
}

extern "C" void kernel_launch(void* const* d_in, const int* in_sizes, int n_in,
                              void* d_out, int out_size) {
    const float* x     = (const float*)d_in[0];
    const float* cv1w  = (const float*)d_in[1];
    const float* bn1g  = (const float*)d_in[2];
    const float* bn1b  = (const float*)d_in[3];
    const float* bn1m  = (const float*)d_in[4];
    const float* bn1v  = (const float*)d_in[5];
    const float* offw  = (const float*)d_in[6];
    const float* offb  = (const float*)d_in[7];
    const float* dcnw  = (const float*)d_in[8];
    const float* dcnb  = (const float*)d_in[9];
    const float* bn2g  = (const float*)d_in[10];
    const float* bn2b  = (const float*)d_in[11];
    const float* bn2m  = (const float*)d_in[12];
    const float* bn2v  = (const float*)d_in[13];
    const float* cv2w  = (const float*)d_in[14];
    const float* bn3g  = (const float*)d_in[15];
    const float* bn3b  = (const float*)d_in[16];
    const float* bn3m  = (const float*)d_in[17];
    const float* bn3v  = (const float*)d_in[18];
    float* out = (float*)d_out;

    prep_kernel<<<256, 256>>>(cv1w, bn1g, bn1b, bn1m, bn1v, offw, dcnw,
                              bn2g, bn2b, bn2m, bn2v, cv2w, bn3g, bn3b, bn3m, bn3v);
    k1_cv1<<<dim3(HW/64, Bn), 256>>>(x);
    k2_offconv<<<dim3(HW/64, Bn), 256>>>(offb);
    k3_dcn<<<dim3(HW/64, Bn), 256>>>(dcnb);
    k4_cv2<<<dim3(HW/64, Bn, 2), 256>>>(x, out);
}

// round 4
// speedup vs baseline: 1.4563x; 1.4563x over previous
#include <cuda_runtime.h>
#include <cuda_bf16.h>
#include <math.h>
#include <stdint.h>

#define Bn 8
#define C1 256
#define CH 128
#define C2 256
#define Hh 80
#define Ww 80
#define HW 6400
#define NT 9
#define KT 1152   /* CH * NT */
#define OC 27
#define NCHK 36   /* K chunks of 32, K reordered as k' = n*128 + c */

// -------- scratch --------
__device__ float g_y1[Bn*CH*HW];
__device__ float g_off[Bn*18*HW];
__device__ float g_mask[Bn*NT*HW];
__device__ float g_z[Bn*CH*HW];
__device__ float g_w1T[C1*CH];
__device__ float g_offT[KT*OC];
__device__ float g_w2T[CH*C2];
__device__ uint32_t g_dcnHi[NCHK*2048];  // bf16x2-packed weights, [ch][o(128)][16 pairs]
__device__ uint32_t g_dcnLo[NCHK*2048];
__device__ float g_s1[CH], g_t1[CH], g_s2[CH], g_t2[CH], g_s3[C2], g_t3[C2];

__device__ __forceinline__ float silu_f(float v) { return v / (1.f + __expf(-v)); }

__device__ __forceinline__ uint32_t pack2bf(float a, float b) {
    __nv_bfloat162 t = __floats2bfloat162_rn(a, b);   // .x = a (low), .y = b (high)
    return *(uint32_t*)&t;
}
__device__ __forceinline__ uint32_t smem_u32(const void* p) {
    uint32_t a; asm("{ .reg .u64 t; cvta.to.shared.u64 t, %1; cvt.u32.u64 %0, t; }" : "=r"(a) : "l"(p));
    return a;
}
#define LDM_X4(r0,r1,r2,r3,addr) \
    asm volatile("ldmatrix.sync.aligned.m8n8.x4.shared.b16 {%0,%1,%2,%3}, [%4];" \
        : "=r"(r0),"=r"(r1),"=r"(r2),"=r"(r3) : "r"(addr))

__device__ __forceinline__ void mma_bf16(float* c, const uint32_t* a, const uint32_t* b) {
    asm volatile(
        "mma.sync.aligned.m16n8k16.row.col.f32.bf16.bf16.f32 "
        "{%0,%1,%2,%3}, {%4,%5,%6,%7}, {%8,%9}, {%0,%1,%2,%3};"
        : "+f"(c[0]), "+f"(c[1]), "+f"(c[2]), "+f"(c[3])
        : "r"(a[0]), "r"(a[1]), "r"(a[2]), "r"(a[3]), "r"(b[0]), "r"(b[1]));
}

// -------- prep --------
__global__ void prep_kernel(const float* __restrict__ cv1w,
                            const float* __restrict__ bn1g, const float* __restrict__ bn1b,
                            const float* __restrict__ bn1m, const float* __restrict__ bn1v,
                            const float* __restrict__ offw, const float* __restrict__ dcnw,
                            const float* __restrict__ bn2g, const float* __restrict__ bn2b,
                            const float* __restrict__ bn2m, const float* __restrict__ bn2v,
                            const float* __restrict__ cv2w,
                            const float* __restrict__ bn3g, const float* __restrict__ bn3b,
                            const float* __restrict__ bn3m, const float* __restrict__ bn3v) {
    int idx0 = blockIdx.x * blockDim.x + threadIdx.x;
    int stride = gridDim.x * blockDim.x;
    for (int i = idx0; i < C1*CH; i += stride) { int c=i/CH, o=i%CH; g_w1T[i] = cv1w[o*C1+c]; }
    for (int i = idx0; i < KT*OC; i += stride) { int k=i/OC, o=i%OC; g_offT[i] = offw[o*KT+k]; }
    for (int i = idx0; i < CH*C2; i += stride) { int c=i/C2, o=i%C2; g_w2T[i] = cv2w[o*CH+c]; }
    // dcn weights: K reordered k' = n*128 + c; chunk ch covers k' = ch*32..+32 (fixed n).
    // pack bf16 hi/lo pairs: [ch][o][kp] kp = pair of consecutive k' (= consecutive c).
    for (int i = idx0; i < NCHK*2048; i += stride) {
        int ch = i >> 11, r = i & 2047;
        int o = r >> 4, kp = r & 15;
        int kk = ch*32 + kp*2;          // k'
        int n = kk >> 7, c = kk & 127;
        float w0 = dcnw[o*KT + c*9 + n];
        float w1 = dcnw[o*KT + (c+1)*9 + n];
        float h0 = __bfloat162float(__float2bfloat16(w0));
        float h1 = __bfloat162float(__float2bfloat16(w1));
        g_dcnHi[i] = pack2bf(h0, h1);
        g_dcnLo[i] = pack2bf(w0 - h0, w1 - h1);
    }
    for (int i = idx0; i < CH; i += stride) {
        float s = bn1g[i] * rsqrtf(bn1v[i] + 1e-5f);
        g_s1[i] = s; g_t1[i] = bn1b[i] - bn1m[i]*s;
        float s2 = bn2g[i] * rsqrtf(bn2v[i] + 1e-5f);
        g_s2[i] = s2; g_t2[i] = bn2b[i] - bn2m[i]*s2;
    }
    for (int i = idx0; i < C2; i += stride) {
        float s = bn3g[i] * rsqrtf(bn3v[i] + 1e-5f);
        g_s3[i] = s; g_t3[i] = bn3b[i] - bn3m[i]*s;
    }
}

// -------- k1: cv1 (1x1) + bn1 + silu --------
__global__ __launch_bounds__(256) void k1_cv1(const float* __restrict__ x) {
    __shared__ float ws[32][128];
    __shared__ float xs[32][64];
    int tid = threadIdx.x;
    int b = blockIdx.y;
    int p0 = blockIdx.x * 64;
    int o0 = (tid >> 4) * 8;
    int px0 = (tid & 15) * 4;
    float acc[8][4] = {};
    const float* xb = x + (size_t)b * C1 * HW + p0;
    for (int kc = 0; kc < C1; kc += 32) {
        for (int i = tid; i < 32*128; i += 256)
            ws[i>>7][i&127] = g_w1T[(kc + (i>>7))*CH + (i&127)];
        for (int i = tid; i < 32*64; i += 256)
            xs[i>>6][i&63] = xb[(kc + (i>>6))*HW + (i&63)];
        __syncthreads();
        #pragma unroll
        for (int kk = 0; kk < 32; kk++) {
            float4 a0 = *(const float4*)&ws[kk][o0];
            float4 a1 = *(const float4*)&ws[kk][o0+4];
            float4 bv = *(const float4*)&xs[kk][px0];
            float av[8] = {a0.x,a0.y,a0.z,a0.w,a1.x,a1.y,a1.z,a1.w};
            float bb[4] = {bv.x,bv.y,bv.z,bv.w};
            #pragma unroll
            for (int i = 0; i < 8; i++)
                #pragma unroll
                for (int j = 0; j < 4; j++) acc[i][j] += av[i]*bb[j];
        }
        __syncthreads();
    }
    #pragma unroll
    for (int i = 0; i < 8; i++) {
        int o = o0 + i;
        float s = g_s1[o], t = g_t1[o];
        float v0 = silu_f(acc[i][0]*s + t);
        float v1 = silu_f(acc[i][1]*s + t);
        float v2 = silu_f(acc[i][2]*s + t);
        float v3 = silu_f(acc[i][3]*s + t);
        *(float4*)(g_y1 + ((size_t)b*CH + o)*HW + p0 + px0) = make_float4(v0,v1,v2,v3);
    }
}

// -------- k2: offset conv --------
__global__ __launch_bounds__(256) void k2_offconv(const float* __restrict__ offb) {
    __shared__ float ws[36][32];
    __shared__ float bs[36][64];
    int tid = threadIdx.x;
    int b = blockIdx.y;
    int p0 = blockIdx.x * 64;
    int o0 = (tid >> 6) * 8;
    int pxid = tid & 63;
    float acc[8] = {};
    const float* y1b = g_y1 + (size_t)b * CH * HW;
    for (int k0 = 0; k0 < KT; k0 += 36) {
        int c0 = k0 / 9;
        for (int i = tid; i < 36*64; i += 256) {
            int kk = i >> 6, pp = i & 63;
            int c = c0 + kk/9, n = kk - (kk/9)*9;
            int p = p0 + pp, h = p/80, w = p - h*80;
            int yy = h + n/3 - 1, xx = w + n%3 - 1;
            bs[kk][pp] = (yy >= 0 && yy < Hh && xx >= 0 && xx < Ww)
                         ? y1b[c*HW + yy*Ww + xx] : 0.f;
        }
        for (int i = tid; i < 36*32; i += 256) {
            int kk = i >> 5, o = i & 31;
            ws[kk][o] = (o < OC) ? g_offT[(k0+kk)*OC + o] : 0.f;
        }
        __syncthreads();
        #pragma unroll
        for (int kk = 0; kk < 36; kk++) {
            float bv = bs[kk][pxid];
            float4 a0 = *(const float4*)&ws[kk][o0];
            float4 a1 = *(const float4*)&ws[kk][o0+4];
            acc[0] += a0.x*bv; acc[1] += a0.y*bv; acc[2] += a0.z*bv; acc[3] += a0.w*bv;
            acc[4] += a1.x*bv; acc[5] += a1.y*bv; acc[6] += a1.z*bv; acc[7] += a1.w*bv;
        }
        __syncthreads();
    }
    int p = p0 + pxid;
    #pragma unroll
    for (int i = 0; i < 8; i++) {
        int o = o0 + i;
        if (o < OC) {
            float v = acc[i] + offb[o];
            if (o < 18) g_off[((size_t)b*18 + o)*HW + p] = v;
            else        g_mask[((size_t)b*NT + (o-18))*HW + p] = 1.f/(1.f + __expf(-v));
        }
    }
}

// -------- k3: DCNv2 via mma.sync bf16 3-term split --------
// smem (dynamic):
//   TBLW [9][128] float4   @0       (18432)
//   TBLI [9][128] int4     @18432   (18432)
//   AH   [128][40] bf16    @36864   (10240)   row stride 80 B
//   AL                     @47104   (10240)
//   BH   [128][40] bf16    @57344   (10240)
//   BL                     @67584   (10240)
#define SM_TBLW 0
#define SM_TBLI 18432
#define SM_AH   36864
#define SM_AL   47104
#define SM_BH   57344
#define SM_BL   67584
#define K3_SMEM 77824

__global__ __launch_bounds__(256, 2) void k3_dcn_mma(const float* __restrict__ dcnb) {
    extern __shared__ char smem[];
    uint32_t sb = smem_u32(smem);
    int tid = threadIdx.x;
    int lane = tid & 31;
    int wid = tid >> 5;
    int b = blockIdx.y;
    int p0 = blockIdx.x * 128;

    float4* tblw = (float4*)(smem + SM_TBLW);
    int4*   tbli = (int4*)(smem + SM_TBLI);
    const float* y1b = g_y1 + (size_t)b * CH * HW;

    // ---- bilinear table: per (tap n, px) ----
    for (int e = tid; e < NT*128; e += 256) {
        int n = e >> 7, px = e & 127;
        int p = p0 + px, h = p / 80, w = p - h * 80;
        float m  = g_mask[((size_t)b*NT + n)*HW + p];
        float dy = g_off[((size_t)b*18 + 2*n    )*HW + p];
        float dx = g_off[((size_t)b*18 + 2*n + 1)*HW + p];
        float py = (float)(h - 1 + n/3) + dy;
        float pxf= (float)(w - 1 + n%3) + dx;
        float y0f = floorf(py), x0f = floorf(pxf);
        float fy = py - y0f, fx = pxf - x0f;
        int y0 = (int)y0f, x0 = (int)x0f;
        int y1i = y0 + 1, x1i = x0 + 1;
        float vy0 = (y0  >= 0 && y0  < Hh) ? 1.f : 0.f;
        float vy1 = (y1i >= 0 && y1i < Hh) ? 1.f : 0.f;
        float vx0 = (x0  >= 0 && x0  < Ww) ? 1.f : 0.f;
        float vx1 = (x1i >= 0 && x1i < Ww) ? 1.f : 0.f;
        int cy0 = min(max(y0, 0), Hh-1) * Ww;
        int cy1 = min(max(y1i,0), Hh-1) * Ww;
        int cx0 = min(max(x0, 0), Ww-1);
        int cx1 = min(max(x1i,0), Ww-1);
        tbli[e] = make_int4(cy0+cx0, cy0+cx1, cy1+cx0, cy1+cx1);
        tblw[e] = make_float4(m*(1.f-fy)*(1.f-fx)*vy0*vx0,
                              m*(1.f-fy)*fx      *vy0*vx1,
                              m*fy*(1.f-fx)      *vy1*vx0,
                              m*fy*fx            *vy1*vx1);
    }
    __syncthreads();

    // warp tiling: warp_o in {0,32,64,96}, warp_p in {0,64}
    int warp_o = (wid >> 1) * 32;
    int warp_p = (wid & 1) * 64;
    // ldmatrix per-lane byte offsets (k0 added per step)
    uint32_t aoff[2], boff[4];
    #pragma unroll
    for (int f = 0; f < 2; f++)
        aoff[f] = SM_AH + (warp_o + f*16 + (lane & 15))*80 + (lane >> 4)*16;
    #pragma unroll
    for (int gp = 0; gp < 4; gp++)
        boff[gp] = SM_BH + (warp_p + (gp*2 + (lane >> 4))*8 + (lane & 7))*80
                 + ((lane >> 3) & 1)*16;

    float c[64];
    #pragma unroll
    for (int i = 0; i < 64; i++) c[i] = 0.f;

    int px = tid & 127;
    int half = tid >> 7;
    uint32_t bsh = sb + SM_BH + px*80 + half*32;   // byte addr of this thread's B half
    uint32_t bsl = sb + SM_BL + px*80 + half*32;

    for (int ch = 0; ch < NCHK; ch++) {
        // ---- fill A (copy packed weights) ----
        {
            const uint4* sh = (const uint4*)(g_dcnHi + ch*2048);
            const uint4* sl = (const uint4*)(g_dcnLo + ch*2048);
            #pragma unroll
            for (int r = 0; r < 2; r++) {
                int i = tid + r*256;           // i < 512; o = i>>2, kq = i&3
                int o = i >> 2, kq = i & 3;
                uint32_t d = o*80 + kq*16;
                *(uint4*)(smem + SM_AH + d) = sh[i];
                *(uint4*)(smem + SM_AL + d) = sl[i];
            }
        }
        // ---- fill B (bilinear gather, bf16 hi/lo) ----
        {
            int n = ch >> 2;
            int c0 = ((ch & 3) << 5) + half*16;
            float4 wv = tblw[(n << 7) + px];
            int4   iv = tbli[(n << 7) + px];
            const float* pb = y1b + c0 * HW;
            #pragma unroll
            for (int q = 0; q < 2; q++) {
                uint4 ph, pl;
                #pragma unroll
                for (int jj = 0; jj < 4; jj++) {
                    const float* pp0 = pb + (q*8 + jj*2) * HW;
                    float v0 = wv.x*__ldg(pp0+iv.x) + wv.y*__ldg(pp0+iv.y)
                             + wv.z*__ldg(pp0+iv.z) + wv.w*__ldg(pp0+iv.w);
                    const float* pp1 = pp0 + HW;
                    float v1 = wv.x*__ldg(pp1+iv.x) + wv.y*__ldg(pp1+iv.y)
                             + wv.z*__ldg(pp1+iv.z) + wv.w*__ldg(pp1+iv.w);
                    float h0 = __bfloat162float(__float2bfloat16(v0));
                    float h1 = __bfloat162float(__float2bfloat16(v1));
                    ((uint32_t*)&ph)[jj] = pack2bf(h0, h1);
                    ((uint32_t*)&pl)[jj] = pack2bf(v0 - h0, v1 - h1);
                }
                asm volatile("st.shared.v4.b32 [%0], {%1,%2,%3,%4};" ::
                    "r"(bsh + q*16), "r"(ph.x), "r"(ph.y), "r"(ph.z), "r"(ph.w));
                asm volatile("st.shared.v4.b32 [%0], {%1,%2,%3,%4};" ::
                    "r"(bsl + q*16), "r"(pl.x), "r"(pl.y), "r"(pl.z), "r"(pl.w));
            }
        }
        __syncthreads();

        // ---- compute: 2 k-steps of 16 ----
        #pragma unroll
        for (int s = 0; s < 2; s++) {
            int kb = s * 32;  // byte offset for k0 = s*16
            uint32_t ah[8], al[8], bh[16], bl[16];
            LDM_X4(ah[0],ah[1],ah[2],ah[3], sb + aoff[0] + kb);
            LDM_X4(ah[4],ah[5],ah[6],ah[7], sb + aoff[1] + kb);
            LDM_X4(al[0],al[1],al[2],al[3], sb + aoff[0] + 10240 + kb);
            LDM_X4(al[4],al[5],al[6],al[7], sb + aoff[1] + 10240 + kb);
            #pragma unroll
            for (int gp = 0; gp < 4; gp++) {
                LDM_X4(bh[gp*4],bh[gp*4+1],bh[gp*4+2],bh[gp*4+3], sb + boff[gp] + kb);
                LDM_X4(bl[gp*4],bl[gp*4+1],bl[gp*4+2],bl[gp*4+3], sb + boff[gp] + 10240 + kb);
            }
            #pragma unroll
            for (int f = 0; f < 2; f++)
                #pragma unroll
                for (int g = 0; g < 8; g++) {
                    float* cc = &c[(f*8 + g)*4];
                    mma_bf16(cc, &ah[f*4], &bh[g*2]);
                    mma_bf16(cc, &al[f*4], &bh[g*2]);
                    mma_bf16(cc, &ah[f*4], &bl[g*2]);
                }
        }
        __syncthreads();
    }

    // ---- epilogue: bn2 + silu ----
    #pragma unroll
    for (int f = 0; f < 2; f++) {
        int o0 = warp_o + f*16 + (lane >> 2);
        #pragma unroll
        for (int half_o = 0; half_o < 2; half_o++) {
            int o = o0 + half_o*8;
            float s = g_s2[o], t = g_t2[o], bias = dcnb[o];
            float* dst = g_z + ((size_t)b*CH + o)*HW + p0 + warp_p + 2*(lane & 3);
            #pragma unroll
            for (int g = 0; g < 8; g++) {
                float v0 = c[(f*8+g)*4 + half_o*2    ];
                float v1 = c[(f*8+g)*4 + half_o*2 + 1];
                float2 r;
                r.x = silu_f((v0 + bias)*s + t);
                r.y = silu_f((v1 + bias)*s + t);
                *(float2*)(dst + g*8) = r;
            }
        }
    }
}

// -------- k4: cv2 (1x1) + bn3 + silu + residual --------
__global__ __launch_bounds__(256) void k4_cv2(const float* __restrict__ x,
                                              float* __restrict__ out) {
    __shared__ float ws[32][128];
    __shared__ float zs[32][64];
    int tid = threadIdx.x;
    int b = blockIdx.y;
    int p0 = blockIdx.x * 64;
    int ob = blockIdx.z * 128;
    int o0 = (tid >> 4) * 8;
    int px0 = (tid & 15) * 4;
    float acc[8][4] = {};
    const float* zb = g_z + (size_t)b * CH * HW + p0;
    for (int kc = 0; kc < CH; kc += 32) {
        for (int i = tid; i < 32*128; i += 256)
            ws[i>>7][i&127] = g_w2T[(kc + (i>>7))*C2 + ob + (i&127)];
        for (int i = tid; i < 32*64; i += 256)
            zs[i>>6][i&63] = zb[(kc + (i>>6))*HW + (i&63)];
        __syncthreads();
        #pragma unroll
        for (int kk = 0; kk < 32; kk++) {
            float4 a0 = *(const float4*)&ws[kk][o0];
            float4 a1 = *(const float4*)&ws[kk][o0+4];
            float4 bv = *(const float4*)&zs[kk][px0];
            float av[8] = {a0.x,a0.y,a0.z,a0.w,a1.x,a1.y,a1.z,a1.w};
            float bb[4] = {bv.x,bv.y,bv.z,bv.w};
            #pragma unroll
            for (int i = 0; i < 8; i++)
                #pragma unroll
                for (int j = 0; j < 4; j++) acc[i][j] += av[i]*bb[j];
        }
        __syncthreads();
    }
    #pragma unroll
    for (int i = 0; i < 8; i++) {
        int o = ob + o0 + i;
        float s = g_s3[o], t = g_t3[o];
        size_t base = ((size_t)b*C2 + o)*HW + p0 + px0;
        float4 xr = *(const float4*)(x + base);
        float v0 = silu_f(acc[i][0]*s + t) + xr.x;
        float v1 = silu_f(acc[i][1]*s + t) + xr.y;
        float v2 = silu_f(acc[i][2]*s + t) + xr.z;
        float v3 = silu_f(acc[i][3]*s + t) + xr.w;
        *(float4*)(out + base) = make_float4(v0,v1,v2,v3);
    }
}

extern "C" void kernel_launch(void* const* d_in, const int* in_sizes, int n_in,
                              void* d_out, int out_size) {
    const float* x     = (const float*)d_in[0];
    const float* cv1w  = (const float*)d_in[1];
    const float* bn1g  = (const float*)d_in[2];
    const float* bn1b  = (const float*)d_in[3];
    const float* bn1m  = (const float*)d_in[4];
    const float* bn1v  = (const float*)d_in[5];
    const float* offw  = (const float*)d_in[6];
    const float* offb  = (const float*)d_in[7];
    const float* dcnw  = (const float*)d_in[8];
    const float* dcnb  = (const float*)d_in[9];
    const float* bn2g  = (const float*)d_in[10];
    const float* bn2b  = (const float*)d_in[11];
    const float* bn2m  = (const float*)d_in[12];
    const float* bn2v  = (const float*)d_in[13];
    const float* cv2w  = (const float*)d_in[14];
    const float* bn3g  = (const float*)d_in[15];
    const float* bn3b  = (const float*)d_in[16];
    const float* bn3m  = (const float*)d_in[17];
    const float* bn3v  = (const float*)d_in[18];
    float* out = (float*)d_out;

    cudaFuncSetAttribute(k3_dcn_mma, cudaFuncAttributeMaxDynamicSharedMemorySize, K3_SMEM);

    prep_kernel<<<256, 256>>>(cv1w, bn1g, bn1b, bn1m, bn1v, offw, dcnw,
                              bn2g, bn2b, bn2m, bn2v, cv2w, bn3g, bn3b, bn3m, bn3v);
    k1_cv1<<<dim3(HW/64, Bn), 256>>>(x);
    k2_offconv<<<dim3(HW/64, Bn), 256>>>(offb);
    k3_dcn_mma<<<dim3(HW/128, Bn), 256, K3_SMEM>>>(dcnb);
    k4_cv2<<<dim3(HW/64, Bn, 2), 256>>>(x, out);
}

// round 5
// speedup vs baseline: 2.4640x; 1.6920x over previous
#include <cuda_runtime.h>
#include <cuda_bf16.h>
#include <math.h>
#include <stdint.h>

#define Bn 8
#define C1 256
#define CH 128
#define C2 256
#define Hh 80
#define Ww 80
#define HW 6400
#define NT 9
#define KT 1152
#define OC 27
#define NCHK 36   /* k3/k2 K chunks of 32, k' = n*128 + c */
#define NCHK1 8   /* k1: K=256 */
#define NCHK4 4   /* k4: K=128 */

// -------- scratch --------
__device__ float g_y1[Bn*CH*HW];
__device__ float g_off[Bn*18*HW];
__device__ float g_mask[Bn*NT*HW];
__device__ float g_z[Bn*CH*HW];
__device__ uint32_t g_dcnHi[NCHK*2048];
__device__ uint32_t g_dcnLo[NCHK*2048];
__device__ uint32_t g_w1Hi[NCHK1*2048];
__device__ uint32_t g_w1Lo[NCHK1*2048];
__device__ uint32_t g_w2Hi[2*NCHK4*2048];
__device__ uint32_t g_w2Lo[2*NCHK4*2048];
__device__ uint32_t g_owHi[NCHK*512];   // offset conv weights, M=32 rows (27 used)
__device__ uint32_t g_owLo[NCHK*512];
__device__ float g_s1[CH], g_t1[CH], g_s2[CH], g_t2[CH], g_s3[C2], g_t3[C2];

__device__ __forceinline__ float silu_f(float v) { return v / (1.f + __expf(-v)); }

__device__ __forceinline__ uint32_t pack2bf(float a, float b) {
    __nv_bfloat162 t = __floats2bfloat162_rn(a, b);
    return *(uint32_t*)&t;
}
__device__ __forceinline__ uint32_t smem_u32(const void* p) {
    uint32_t a; asm("{ .reg .u64 t; cvta.to.shared.u64 t, %1; cvt.u32.u64 %0, t; }" : "=r"(a) : "l"(p));
    return a;
}
#define LDM_X4(r0,r1,r2,r3,addr) \
    asm volatile("ldmatrix.sync.aligned.m8n8.x4.shared.b16 {%0,%1,%2,%3}, [%4];" \
        : "=r"(r0),"=r"(r1),"=r"(r2),"=r"(r3) : "r"(addr))

__device__ __forceinline__ void mma_bf16(float* c, const uint32_t* a, const uint32_t* b) {
    asm volatile(
        "mma.sync.aligned.m16n8k16.row.col.f32.bf16.bf16.f32 "
        "{%0,%1,%2,%3}, {%4,%5,%6,%7}, {%8,%9}, {%0,%1,%2,%3};"
        : "+f"(c[0]), "+f"(c[1]), "+f"(c[2]), "+f"(c[3])
        : "r"(a[0]), "r"(a[1]), "r"(a[2]), "r"(a[3]), "r"(b[0]), "r"(b[1]));
}

// pack a fp32 weight into hi/lo bf16 pair entries
__device__ __forceinline__ void split_pack(float w0, float w1, uint32_t* hi, uint32_t* lo) {
    float h0 = __bfloat162float(__float2bfloat16(w0));
    float h1 = __bfloat162float(__float2bfloat16(w1));
    *hi = pack2bf(h0, h1);
    *lo = pack2bf(w0 - h0, w1 - h1);
}

// -------- prep --------
__global__ void prep_kernel(const float* __restrict__ cv1w,
                            const float* __restrict__ bn1g, const float* __restrict__ bn1b,
                            const float* __restrict__ bn1m, const float* __restrict__ bn1v,
                            const float* __restrict__ offw, const float* __restrict__ dcnw,
                            const float* __restrict__ bn2g, const float* __restrict__ bn2b,
                            const float* __restrict__ bn2m, const float* __restrict__ bn2v,
                            const float* __restrict__ cv2w,
                            const float* __restrict__ bn3g, const float* __restrict__ bn3b,
                            const float* __restrict__ bn3m, const float* __restrict__ bn3v) {
    int idx0 = blockIdx.x * blockDim.x + threadIdx.x;
    int stride = gridDim.x * blockDim.x;
    // dcn: [ch][o(128)][kp(16)], k' = n*128 + c
    for (int i = idx0; i < NCHK*2048; i += stride) {
        int ch = i >> 11, r = i & 2047;
        int o = r >> 4, kp = r & 15;
        int kk = ch*32 + kp*2;
        int n = kk >> 7, c = kk & 127;
        split_pack(dcnw[o*KT + c*9 + n], dcnw[o*KT + (c+1)*9 + n], &g_dcnHi[i], &g_dcnLo[i]);
    }
    // cv1: [ch][o(128)][kp(16)], k = input channel
    for (int i = idx0; i < NCHK1*2048; i += stride) {
        int ch = i >> 11, r = i & 2047;
        int o = r >> 4, kp = r & 15;
        int c = ch*32 + kp*2;
        split_pack(cv1w[o*C1 + c], cv1w[o*C1 + c + 1], &g_w1Hi[i], &g_w1Lo[i]);
    }
    // cv2: [z][ch][o(128)][kp(16)]
    for (int i = idx0; i < 2*NCHK4*2048; i += stride) {
        int z = i >> 13, r1 = i & 8191;
        int ch = r1 >> 11, r = r1 & 2047;
        int o = r >> 4, kp = r & 15;
        int c = ch*32 + kp*2;
        split_pack(cv2w[(z*128+o)*CH + c], cv2w[(z*128+o)*CH + c + 1], &g_w2Hi[i], &g_w2Lo[i]);
    }
    // off conv: [ch][o(32, 27 used)][kp(16)], k' = n*128 + c
    for (int i = idx0; i < NCHK*512; i += stride) {
        int ch = i >> 9, r = i & 511;
        int o = r >> 4, kp = r & 15;
        int kk = ch*32 + kp*2;
        int n = kk >> 7, c = kk & 127;
        float w0 = (o < OC) ? offw[o*KT + c*9 + n] : 0.f;
        float w1 = (o < OC) ? offw[o*KT + (c+1)*9 + n] : 0.f;
        split_pack(w0, w1, &g_owHi[i], &g_owLo[i]);
    }
    for (int i = idx0; i < CH; i += stride) {
        float s = bn1g[i] * rsqrtf(bn1v[i] + 1e-5f);
        g_s1[i] = s; g_t1[i] = bn1b[i] - bn1m[i]*s;
        float s2 = bn2g[i] * rsqrtf(bn2v[i] + 1e-5f);
        g_s2[i] = s2; g_t2[i] = bn2b[i] - bn2m[i]*s2;
    }
    for (int i = idx0; i < C2; i += stride) {
        float s = bn3g[i] * rsqrtf(bn3v[i] + 1e-5f);
        g_s3[i] = s; g_t3[i] = bn3b[i] - bn3m[i]*s;
    }
}

// ======== k1: cv1 (1x1, K=256) + bn1 + silu via mma ========
// smem: AH[128][40]bf16 @0 (10240), AL @10240, BH @20480, BL @30720
__global__ __launch_bounds__(256, 2) void k1_mma(const float* __restrict__ x) {
    __shared__ char sm[40960];
    uint32_t sb = smem_u32(sm);
    int tid = threadIdx.x;
    int lane = tid & 31;
    int wid = tid >> 5;
    int b = blockIdx.y;
    int p0 = blockIdx.x * 128;

    int warp_o = (wid >> 1) * 32;
    int warp_p = (wid & 1) * 64;
    uint32_t aoff[2], boff[4];
    #pragma unroll
    for (int f = 0; f < 2; f++)
        aoff[f] = (warp_o + f*16 + (lane & 15))*80 + (lane >> 4)*16;
    #pragma unroll
    for (int gp = 0; gp < 4; gp++)
        boff[gp] = 20480 + (warp_p + (gp*2 + (lane >> 4))*8 + (lane & 7))*80
                 + ((lane >> 3) & 1)*16;

    float c[64];
    #pragma unroll
    for (int i = 0; i < 64; i++) c[i] = 0.f;

    int px = tid & 127;
    int half = tid >> 7;
    uint32_t bsh = sb + 20480 + px*80 + half*32;
    uint32_t bsl = sb + 30720 + px*80 + half*32;
    const float* xb = x + (size_t)b * C1 * HW + p0 + px;

    for (int ch = 0; ch < NCHK1; ch++) {
        // A fill
        {
            const uint4* sh = (const uint4*)(g_w1Hi + ch*2048);
            const uint4* sl = (const uint4*)(g_w1Lo + ch*2048);
            #pragma unroll
            for (int r = 0; r < 2; r++) {
                int i = tid + r*256;
                uint32_t d = (i >> 2)*80 + (i & 3)*16;
                *(uint4*)(sm + d) = sh[i];
                *(uint4*)(sm + 10240 + d) = sl[i];
            }
        }
        // B fill: direct loads of x
        {
            int c0 = ch*32 + half*16;
            #pragma unroll
            for (int q = 0; q < 2; q++) {
                uint4 ph, pl;
                #pragma unroll
                for (int jj = 0; jj < 4; jj++) {
                    int cc = c0 + q*8 + jj*2;
                    float v0 = __ldg(xb + (size_t)cc*HW);
                    float v1 = __ldg(xb + (size_t)(cc+1)*HW);
                    split_pack(v0, v1, &((uint32_t*)&ph)[jj], &((uint32_t*)&pl)[jj]);
                }
                asm volatile("st.shared.v4.b32 [%0], {%1,%2,%3,%4};" ::
                    "r"(bsh + q*16), "r"(ph.x), "r"(ph.y), "r"(ph.z), "r"(ph.w));
                asm volatile("st.shared.v4.b32 [%0], {%1,%2,%3,%4};" ::
                    "r"(bsl + q*16), "r"(pl.x), "r"(pl.y), "r"(pl.z), "r"(pl.w));
            }
        }
        __syncthreads();
        #pragma unroll
        for (int s = 0; s < 2; s++) {
            int kb = s * 32;
            uint32_t ah[8], al[8], bh[16], bl[16];
            LDM_X4(ah[0],ah[1],ah[2],ah[3], sb + aoff[0] + kb);
            LDM_X4(ah[4],ah[5],ah[6],ah[7], sb + aoff[1] + kb);
            LDM_X4(al[0],al[1],al[2],al[3], sb + aoff[0] + 10240 + kb);
            LDM_X4(al[4],al[5],al[6],al[7], sb + aoff[1] + 10240 + kb);
            #pragma unroll
            for (int gp = 0; gp < 4; gp++) {
                LDM_X4(bh[gp*4],bh[gp*4+1],bh[gp*4+2],bh[gp*4+3], sb + boff[gp] + kb);
                LDM_X4(bl[gp*4],bl[gp*4+1],bl[gp*4+2],bl[gp*4+3], sb + boff[gp] + 10240 + kb);
            }
            #pragma unroll
            for (int f = 0; f < 2; f++)
                #pragma unroll
                for (int g = 0; g < 8; g++) {
                    float* cc = &c[(f*8 + g)*4];
                    mma_bf16(cc, &ah[f*4], &bh[g*2]);
                    mma_bf16(cc, &al[f*4], &bh[g*2]);
                    mma_bf16(cc, &ah[f*4], &bl[g*2]);
                }
        }
        __syncthreads();
    }
    #pragma unroll
    for (int f = 0; f < 2; f++) {
        int o0 = warp_o + f*16 + (lane >> 2);
        #pragma unroll
        for (int ho = 0; ho < 2; ho++) {
            int o = o0 + ho*8;
            float s = g_s1[o], t = g_t1[o];
            float* dst = g_y1 + ((size_t)b*CH + o)*HW + p0 + warp_p + 2*(lane & 3);
            #pragma unroll
            for (int g = 0; g < 8; g++) {
                float2 r;
                r.x = silu_f(c[(f*8+g)*4 + ho*2    ]*s + t);
                r.y = silu_f(c[(f*8+g)*4 + ho*2 + 1]*s + t);
                *(float2*)(dst + g*8) = r;
            }
        }
    }
}

// ======== k2: offset conv (M=32, K=1152, tap-major) via mma ========
// smem: AH[32][40] @0 (2560), AL @2560, BH[128][40] @5120 (10240), BL @15360
__global__ __launch_bounds__(256, 2) void k2_mma(const float* __restrict__ offb) {
    __shared__ char sm[25600];
    uint32_t sb = smem_u32(sm);
    int tid = threadIdx.x;
    int lane = tid & 31;
    int wid = tid >> 5;
    int b = blockIdx.y;
    int p0 = blockIdx.x * 128;

    int warp_p = wid * 16;
    uint32_t aoff[2], boff;
    #pragma unroll
    for (int f = 0; f < 2; f++)
        aoff[f] = (f*16 + (lane & 15))*80 + (lane >> 4)*16;
    boff = 5120 + (warp_p + (lane >> 4)*8 + (lane & 7))*80 + ((lane >> 3) & 1)*16;

    float c[16];
    #pragma unroll
    for (int i = 0; i < 16; i++) c[i] = 0.f;

    int px = tid & 127;
    int half = tid >> 7;
    uint32_t bsh = sb + 5120 + px*80 + half*32;
    uint32_t bsl = sb + 15360 + px*80 + half*32;
    const float* y1b = g_y1 + (size_t)b * CH * HW;
    int p = p0 + px, h = p / 80, w = p - h*80;

    for (int ch = 0; ch < NCHK; ch++) {
        // A fill (32 rows)
        if (tid < 128) {
            const uint4* sh = (const uint4*)(g_owHi + ch*512);
            const uint4* sl = (const uint4*)(g_owLo + ch*512);
            uint32_t d = (tid >> 2)*80 + (tid & 3)*16;
            *(uint4*)(sm + d) = sh[tid];
            *(uint4*)(sm + 2560 + d) = sl[tid];
        }
        // B fill: statically shifted y1 read (fixed tap)
        {
            int n = ch >> 2;
            int c0 = ((ch & 3) << 5) + half*16;
            int yy = h + n/3 - 1, xx = w + n%3 - 1;
            bool valid = (yy >= 0 && yy < Hh && xx >= 0 && xx < Ww);
            const float* src = y1b + (size_t)c0*HW + yy*Ww + xx;
            #pragma unroll
            for (int q = 0; q < 2; q++) {
                uint4 ph, pl;
                #pragma unroll
                for (int jj = 0; jj < 4; jj++) {
                    int cc = q*8 + jj*2;
                    float v0 = valid ? __ldg(src + (size_t)cc*HW) : 0.f;
                    float v1 = valid ? __ldg(src + (size_t)(cc+1)*HW) : 0.f;
                    split_pack(v0, v1, &((uint32_t*)&ph)[jj], &((uint32_t*)&pl)[jj]);
                }
                asm volatile("st.shared.v4.b32 [%0], {%1,%2,%3,%4};" ::
                    "r"(bsh + q*16), "r"(ph.x), "r"(ph.y), "r"(ph.z), "r"(ph.w));
                asm volatile("st.shared.v4.b32 [%0], {%1,%2,%3,%4};" ::
                    "r"(bsl + q*16), "r"(pl.x), "r"(pl.y), "r"(pl.z), "r"(pl.w));
            }
        }
        __syncthreads();
        #pragma unroll
        for (int s = 0; s < 2; s++) {
            int kb = s * 32;
            uint32_t ah[8], al[8], bh[4], bl[4];
            LDM_X4(ah[0],ah[1],ah[2],ah[3], sb + aoff[0] + kb);
            LDM_X4(ah[4],ah[5],ah[6],ah[7], sb + aoff[1] + kb);
            LDM_X4(al[0],al[1],al[2],al[3], sb + aoff[0] + 2560 + kb);
            LDM_X4(al[4],al[5],al[6],al[7], sb + aoff[1] + 2560 + kb);
            LDM_X4(bh[0],bh[1],bh[2],bh[3], sb + boff + kb);
            LDM_X4(bl[0],bl[1],bl[2],bl[3], sb + boff + 10240 + kb);
            #pragma unroll
            for (int f = 0; f < 2; f++)
                #pragma unroll
                for (int g = 0; g < 2; g++) {
                    float* cc = &c[(f*2 + g)*4];
                    mma_bf16(cc, &ah[f*4], &bh[g*2]);
                    mma_bf16(cc, &al[f*4], &bh[g*2]);
                    mma_bf16(cc, &ah[f*4], &bl[g*2]);
                }
        }
        __syncthreads();
    }
    #pragma unroll
    for (int f = 0; f < 2; f++) {
        #pragma unroll
        for (int ho = 0; ho < 2; ho++) {
            int o = f*16 + (lane >> 2) + ho*8;
            if (o < OC) {
                float bias = offb[o];
                int pp = p0 + warp_p + 2*(lane & 3);
                #pragma unroll
                for (int g = 0; g < 2; g++) {
                    float v0 = c[(f*2+g)*4 + ho*2    ] + bias;
                    float v1 = c[(f*2+g)*4 + ho*2 + 1] + bias;
                    if (o < 18) {
                        float* dst = g_off + ((size_t)b*18 + o)*HW + pp + g*8;
                        *(float2*)dst = make_float2(v0, v1);
                    } else {
                        float* dst = g_mask + ((size_t)b*NT + (o-18))*HW + pp + g*8;
                        *(float2*)dst = make_float2(1.f/(1.f + __expf(-v0)),
                                                    1.f/(1.f + __expf(-v1)));
                    }
                }
            }
        }
    }
}

// ======== k3: DCNv2 via mma (unchanged from R3) ========
#define SM_TBLW 0
#define SM_TBLI 18432
#define SM_AH   36864
#define SM_AL   47104
#define SM_BH   57344
#define SM_BL   67584
#define K3_SMEM 77824

__global__ __launch_bounds__(256, 2) void k3_dcn_mma(const float* __restrict__ dcnb) {
    extern __shared__ char smem[];
    uint32_t sb = smem_u32(smem);
    int tid = threadIdx.x;
    int lane = tid & 31;
    int wid = tid >> 5;
    int b = blockIdx.y;
    int p0 = blockIdx.x * 128;

    float4* tblw = (float4*)(smem + SM_TBLW);
    int4*   tbli = (int4*)(smem + SM_TBLI);
    const float* y1b = g_y1 + (size_t)b * CH * HW;

    for (int e = tid; e < NT*128; e += 256) {
        int n = e >> 7, px = e & 127;
        int p = p0 + px, h = p / 80, w = p - h * 80;
        float m  = g_mask[((size_t)b*NT + n)*HW + p];
        float dy = g_off[((size_t)b*18 + 2*n    )*HW + p];
        float dx = g_off[((size_t)b*18 + 2*n + 1)*HW + p];
        float py = (float)(h - 1 + n/3) + dy;
        float pxf= (float)(w - 1 + n%3) + dx;
        float y0f = floorf(py), x0f = floorf(pxf);
        float fy = py - y0f, fx = pxf - x0f;
        int y0 = (int)y0f, x0 = (int)x0f;
        int y1i = y0 + 1, x1i = x0 + 1;
        float vy0 = (y0  >= 0 && y0  < Hh) ? 1.f : 0.f;
        float vy1 = (y1i >= 0 && y1i < Hh) ? 1.f : 0.f;
        float vx0 = (x0  >= 0 && x0  < Ww) ? 1.f : 0.f;
        float vx1 = (x1i >= 0 && x1i < Ww) ? 1.f : 0.f;
        int cy0 = min(max(y0, 0), Hh-1) * Ww;
        int cy1 = min(max(y1i,0), Hh-1) * Ww;
        int cx0 = min(max(x0, 0), Ww-1);
        int cx1 = min(max(x1i,0), Ww-1);
        tbli[e] = make_int4(cy0+cx0, cy0+cx1, cy1+cx0, cy1+cx1);
        tblw[e] = make_float4(m*(1.f-fy)*(1.f-fx)*vy0*vx0,
                              m*(1.f-fy)*fx      *vy0*vx1,
                              m*fy*(1.f-fx)      *vy1*vx0,
                              m*fy*fx            *vy1*vx1);
    }
    __syncthreads();

    int warp_o = (wid >> 1) * 32;
    int warp_p = (wid & 1) * 64;
    uint32_t aoff[2], boff[4];
    #pragma unroll
    for (int f = 0; f < 2; f++)
        aoff[f] = SM_AH + (warp_o + f*16 + (lane & 15))*80 + (lane >> 4)*16;
    #pragma unroll
    for (int gp = 0; gp < 4; gp++)
        boff[gp] = SM_BH + (warp_p + (gp*2 + (lane >> 4))*8 + (lane & 7))*80
                 + ((lane >> 3) & 1)*16;

    float c[64];
    #pragma unroll
    for (int i = 0; i < 64; i++) c[i] = 0.f;

    int px = tid & 127;
    int half = tid >> 7;
    uint32_t bsh = sb + SM_BH + px*80 + half*32;
    uint32_t bsl = sb + SM_BL + px*80 + half*32;

    for (int ch = 0; ch < NCHK; ch++) {
        {
            const uint4* sh = (const uint4*)(g_dcnHi + ch*2048);
            const uint4* sl = (const uint4*)(g_dcnLo + ch*2048);
            #pragma unroll
            for (int r = 0; r < 2; r++) {
                int i = tid + r*256;
                int o = i >> 2, kq = i & 3;
                uint32_t d = o*80 + kq*16;
                *(uint4*)(smem + SM_AH + d) = sh[i];
                *(uint4*)(smem + SM_AL + d) = sl[i];
            }
        }
        {
            int n = ch >> 2;
            int c0 = ((ch & 3) << 5) + half*16;
            float4 wv = tblw[(n << 7) + px];
            int4   iv = tbli[(n << 7) + px];
            const float* pb = y1b + c0 * HW;
            #pragma unroll
            for (int q = 0; q < 2; q++) {
                uint4 ph, pl;
                #pragma unroll
                for (int jj = 0; jj < 4; jj++) {
                    const float* pp0 = pb + (q*8 + jj*2) * HW;
                    float v0 = wv.x*__ldg(pp0+iv.x) + wv.y*__ldg(pp0+iv.y)
                             + wv.z*__ldg(pp0+iv.z) + wv.w*__ldg(pp0+iv.w);
                    const float* pp1 = pp0 + HW;
                    float v1 = wv.x*__ldg(pp1+iv.x) + wv.y*__ldg(pp1+iv.y)
                             + wv.z*__ldg(pp1+iv.z) + wv.w*__ldg(pp1+iv.w);
                    split_pack(v0, v1, &((uint32_t*)&ph)[jj], &((uint32_t*)&pl)[jj]);
                }
                asm volatile("st.shared.v4.b32 [%0], {%1,%2,%3,%4};" ::
                    "r"(bsh + q*16), "r"(ph.x), "r"(ph.y), "r"(ph.z), "r"(ph.w));
                asm volatile("st.shared.v4.b32 [%0], {%1,%2,%3,%4};" ::
                    "r"(bsl + q*16), "r"(pl.x), "r"(pl.y), "r"(pl.z), "r"(pl.w));
            }
        }
        __syncthreads();

        #pragma unroll
        for (int s = 0; s < 2; s++) {
            int kb = s * 32;
            uint32_t ah[8], al[8], bh[16], bl[16];
            LDM_X4(ah[0],ah[1],ah[2],ah[3], sb + aoff[0] + kb);
            LDM_X4(ah[4],ah[5],ah[6],ah[7], sb + aoff[1] + kb);
            LDM_X4(al[0],al[1],al[2],al[3], sb + aoff[0] + 10240 + kb);
            LDM_X4(al[4],al[5],al[6],al[7], sb + aoff[1] + 10240 + kb);
            #pragma unroll
            for (int gp = 0; gp < 4; gp++) {
                LDM_X4(bh[gp*4],bh[gp*4+1],bh[gp*4+2],bh[gp*4+3], sb + boff[gp] + kb);
                LDM_X4(bl[gp*4],bl[gp*4+1],bl[gp*4+2],bl[gp*4+3], sb + boff[gp] + 10240 + kb);
            }
            #pragma unroll
            for (int f = 0; f < 2; f++)
                #pragma unroll
                for (int g = 0; g < 8; g++) {
                    float* cc = &c[(f*8 + g)*4];
                    mma_bf16(cc, &ah[f*4], &bh[g*2]);
                    mma_bf16(cc, &al[f*4], &bh[g*2]);
                    mma_bf16(cc, &ah[f*4], &bl[g*2]);
                }
        }
        __syncthreads();
    }

    #pragma unroll
    for (int f = 0; f < 2; f++) {
        int o0 = warp_o + f*16 + (lane >> 2);
        #pragma unroll
        for (int ho = 0; ho < 2; ho++) {
            int o = o0 + ho*8;
            float s = g_s2[o], t = g_t2[o], bias = dcnb[o];
            float* dst = g_z + ((size_t)b*CH + o)*HW + p0 + warp_p + 2*(lane & 3);
            #pragma unroll
            for (int g = 0; g < 8; g++) {
                float v0 = c[(f*8+g)*4 + ho*2    ];
                float v1 = c[(f*8+g)*4 + ho*2 + 1];
                float2 r;
                r.x = silu_f((v0 + bias)*s + t);
                r.y = silu_f((v1 + bias)*s + t);
                *(float2*)(dst + g*8) = r;
            }
        }
    }
}

// ======== k4: cv2 (1x1, K=128) + bn3 + silu + residual via mma ========
__global__ __launch_bounds__(256, 2) void k4_mma(const float* __restrict__ x,
                                                 float* __restrict__ out) {
    __shared__ char sm[40960];
    uint32_t sb = smem_u32(sm);
    int tid = threadIdx.x;
    int lane = tid & 31;
    int wid = tid >> 5;
    int b = blockIdx.y;
    int p0 = blockIdx.x * 128;
    int z = blockIdx.z;

    int warp_o = (wid >> 1) * 32;
    int warp_p = (wid & 1) * 64;
    uint32_t aoff[2], boff[4];
    #pragma unroll
    for (int f = 0; f < 2; f++)
        aoff[f] = (warp_o + f*16 + (lane & 15))*80 + (lane >> 4)*16;
    #pragma unroll
    for (int gp = 0; gp < 4; gp++)
        boff[gp] = 20480 + (warp_p + (gp*2 + (lane >> 4))*8 + (lane & 7))*80
                 + ((lane >> 3) & 1)*16;

    float c[64];
    #pragma unroll
    for (int i = 0; i < 64; i++) c[i] = 0.f;

    int px = tid & 127;
    int half = tid >> 7;
    uint32_t bsh = sb + 20480 + px*80 + half*32;
    uint32_t bsl = sb + 30720 + px*80 + half*32;
    const float* zb = g_z + (size_t)b * CH * HW + p0 + px;

    for (int ch = 0; ch < NCHK4; ch++) {
        {
            const uint4* sh = (const uint4*)(g_w2Hi + (z*NCHK4 + ch)*2048);
            const uint4* sl = (const uint4*)(g_w2Lo + (z*NCHK4 + ch)*2048);
            #pragma unroll
            for (int r = 0; r < 2; r++) {
                int i = tid + r*256;
                uint32_t d = (i >> 2)*80 + (i & 3)*16;
                *(uint4*)(sm + d) = sh[i];
                *(uint4*)(sm + 10240 + d) = sl[i];
            }
        }
        {
            int c0 = ch*32 + half*16;
            #pragma unroll
            for (int q = 0; q < 2; q++) {
                uint4 ph, pl;
                #pragma unroll
                for (int jj = 0; jj < 4; jj++) {
                    int cc = c0 + q*8 + jj*2;
                    float v0 = __ldg(zb + (size_t)cc*HW);
                    float v1 = __ldg(zb + (size_t)(cc+1)*HW);
                    split_pack(v0, v1, &((uint32_t*)&ph)[jj], &((uint32_t*)&pl)[jj]);
                }
                asm volatile("st.shared.v4.b32 [%0], {%1,%2,%3,%4};" ::
                    "r"(bsh + q*16), "r"(ph.x), "r"(ph.y), "r"(ph.z), "r"(ph.w));
                asm volatile("st.shared.v4.b32 [%0], {%1,%2,%3,%4};" ::
                    "r"(bsl + q*16), "r"(pl.x), "r"(pl.y), "r"(pl.z), "r"(pl.w));
            }
        }
        __syncthreads();
        #pragma unroll
        for (int s = 0; s < 2; s++) {
            int kb = s * 32;
            uint32_t ah[8], al[8], bh[16], bl[16];
            LDM_X4(ah[0],ah[1],ah[2],ah[3], sb + aoff[0] + kb);
            LDM_X4(ah[4],ah[5],ah[6],ah[7], sb + aoff[1] + kb);
            LDM_X4(al[0],al[1],al[2],al[3], sb + aoff[0] + 10240 + kb);
            LDM_X4(al[4],al[5],al[6],al[7], sb + aoff[1] + 10240 + kb);
            #pragma unroll
            for (int gp = 0; gp < 4; gp++) {
                LDM_X4(bh[gp*4],bh[gp*4+1],bh[gp*4+2],bh[gp*4+3], sb + boff[gp] + kb);
                LDM_X4(bl[gp*4],bl[gp*4+1],bl[gp*4+2],bl[gp*4+3], sb + boff[gp] + 10240 + kb);
            }
            #pragma unroll
            for (int f = 0; f < 2; f++)
                #pragma unroll
                for (int g = 0; g < 8; g++) {
                    float* cc = &c[(f*8 + g)*4];
                    mma_bf16(cc, &ah[f*4], &bh[g*2]);
                    mma_bf16(cc, &al[f*4], &bh[g*2]);
                    mma_bf16(cc, &ah[f*4], &bl[g*2]);
                }
        }
        __syncthreads();
    }
    #pragma unroll
    for (int f = 0; f < 2; f++) {
        #pragma unroll
        for (int ho = 0; ho < 2; ho++) {
            int o = z*128 + warp_o + f*16 + (lane >> 2) + ho*8;
            float s = g_s3[o], t = g_t3[o];
            size_t base = ((size_t)b*C2 + o)*HW + p0 + warp_p + 2*(lane & 3);
            #pragma unroll
            for (int g = 0; g < 8; g++) {
                float2 xr = *(const float2*)(x + base + g*8);
                float2 r;
                r.x = silu_f(c[(f*8+g)*4 + ho*2    ]*s + t) + xr.x;
                r.y = silu_f(c[(f*8+g)*4 + ho*2 + 1]*s + t) + xr.y;
                *(float2*)(out + base + g*8) = r;
            }
        }
    }
}

extern "C" void kernel_launch(void* const* d_in, const int* in_sizes, int n_in,
                              void* d_out, int out_size) {
    const float* x     = (const float*)d_in[0];
    const float* cv1w  = (const float*)d_in[1];
    const float* bn1g  = (const float*)d_in[2];
    const float* bn1b  = (const float*)d_in[3];
    const float* bn1m  = (const float*)d_in[4];
    const float* bn1v  = (const float*)d_in[5];
    const float* offw  = (const float*)d_in[6];
    const float* offb  = (const float*)d_in[7];
    const float* dcnw  = (const float*)d_in[8];
    const float* dcnb  = (const float*)d_in[9];
    const float* bn2g  = (const float*)d_in[10];
    const float* bn2b  = (const float*)d_in[11];
    const float* bn2m  = (const float*)d_in[12];
    const float* bn2v  = (const float*)d_in[13];
    const float* cv2w  = (const float*)d_in[14];
    const float* bn3g  = (const float*)d_in[15];
    const float* bn3b  = (const float*)d_in[16];
    const float* bn3m  = (const float*)d_in[17];
    const float* bn3v  = (const float*)d_in[18];
    float* out = (float*)d_out;

    cudaFuncSetAttribute(k3_dcn_mma, cudaFuncAttributeMaxDynamicSharedMemorySize, K3_SMEM);

    prep_kernel<<<256, 256>>>(cv1w, bn1g, bn1b, bn1m, bn1v, offw, dcnw,
                              bn2g, bn2b, bn2m, bn2v, cv2w, bn3g, bn3b, bn3m, bn3v);
    k1_mma<<<dim3(HW/128, Bn), 256>>>(x);
    k2_mma<<<dim3(HW/128, Bn), 256>>>(offb);
    k3_dcn_mma<<<dim3(HW/128, Bn), 256, K3_SMEM>>>(dcnb);
    k4_mma<<<dim3(HW/128, Bn, 2), 256>>>(x, out);
}